// round 3
// baseline (speedup 1.0000x reference)
#include <cuda_runtime.h>

#define NB  4
#define CX  3
#define HH  512
#define WW  512
#define HW  (HH * WW)
#define RAD 4
#define EPSV 1e-8f
#define SEG 32

// Scratch (static device arrays; no runtime allocation).
__device__ float g_s1[13 * NB * HW];  // 13 product channels, horizontally box-summed
__device__ float g_s2[4 * NB * HW];   // A0,A1,A2,b per pixel
__device__ float g_s3[4 * NB * HW];   // horizontally box-summed A,b

// ---------------------------------------------------------------------------
// K1: per-row horizontal 9-tap box sums of the 13 product channels.
// One block per (row, n). Products built in shared, then clamped 9-tap sums.
// ---------------------------------------------------------------------------
__global__ void k1_hbox(const float* __restrict__ x, const float* __restrict__ y) {
    const int row = blockIdx.x;
    const int n   = blockIdx.y;
    __shared__ float sp[13][WW];

    const float* xb = x + (size_t)n * CX * HW + (size_t)row * WW;
    const float* yb = y + (size_t)n * HW + (size_t)row * WW;

    for (int j = threadIdx.x; j < WW; j += blockDim.x) {
        float x0 = xb[j];
        float x1 = xb[HW + j];
        float x2 = xb[2 * HW + j];
        float yy = yb[j];
        sp[0][j]  = x0;      sp[1][j]  = x1;      sp[2][j]  = x2;
        sp[3][j]  = yy;
        sp[4][j]  = yy * x0; sp[5][j]  = yy * x1; sp[6][j]  = yy * x2;
        sp[7][j]  = x0 * x0; sp[8][j]  = x0 * x1; sp[9][j]  = x0 * x2;
        sp[10][j] = x1 * x1; sp[11][j] = x1 * x2; sp[12][j] = x2 * x2;
    }
    __syncthreads();

    const int ob = n * 13 * HW + row * WW;
    for (int j = threadIdx.x; j < WW; j += blockDim.x) {
        int j0 = j - RAD; if (j0 < 0) j0 = 0;
        int j1 = j + RAD; if (j1 > WW - 1) j1 = WW - 1;
        float s[13];
        #pragma unroll
        for (int c = 0; c < 13; c++) s[c] = 0.f;
        for (int t = j0; t <= j1; t++) {
            #pragma unroll
            for (int c = 0; c < 13; c++) s[c] += sp[c][t];
        }
        #pragma unroll
        for (int c = 0; c < 13; c++) g_s1[ob + c * HW + j] = s[c];
    }
}

// ---------------------------------------------------------------------------
// K2: vertical sliding-window sums (registers) + per-pixel 3x3 solve.
// Each thread owns one column for a SEG-row segment.
// ---------------------------------------------------------------------------
__global__ void k2_vsolve() {
    const int col = blockIdx.x * blockDim.x + threadIdx.x;
    const int n   = blockIdx.y;
    const int s0  = blockIdx.z * SEG;
    if (col >= WW) return;

    const int base = n * 13 * HW + col;
    float s[13];
    #pragma unroll
    for (int c = 0; c < 13; c++) s[c] = 0.f;

    int rlo = s0 - RAD; if (rlo < 0) rlo = 0;
    for (int rr = rlo; rr < s0 + RAD; rr++) {
        #pragma unroll
        for (int c = 0; c < 13; c++) s[c] += g_s1[base + c * HW + rr * WW];
    }

    int cl = col - RAD; if (cl < 0) cl = 0;
    int ch = col + RAD; if (ch > WW - 1) ch = WW - 1;
    const int nx = ch - cl + 1;
    const int ob = n * 4 * HW + col;

    for (int row = s0; row < s0 + SEG; row++) {
        if (row + RAD < HH) {
            #pragma unroll
            for (int c = 0; c < 13; c++) s[c] += g_s1[base + c * HW + (row + RAD) * WW];
        }
        int r0 = row - RAD; if (r0 < 0) r0 = 0;
        int r1 = row + RAD; if (r1 > HH - 1) r1 = HH - 1;
        const int ny = r1 - r0 + 1;
        const float invN = 1.f / (float)(nx * ny);

        float mx0 = s[0] * invN, mx1 = s[1] * invN, mx2 = s[2] * invN;
        float my  = s[3] * invN;
        float cy0 = s[4] * invN - my * mx0;
        float cy1 = s[5] * invN - my * mx1;
        float cy2 = s[6] * invN - my * mx2;
        float m00 = s[7]  * invN - mx0 * mx0 + EPSV;
        float m01 = s[8]  * invN - mx0 * mx1;
        float m02 = s[9]  * invN - mx0 * mx2;
        float m11 = s[10] * invN - mx1 * mx1 + EPSV;
        float m12 = s[11] * invN - mx1 * mx2;
        float m22 = s[12] * invN - mx2 * mx2 + EPSV;

        float c00 = m11 * m22 - m12 * m12;
        float c01 = m02 * m12 - m01 * m22;
        float c02 = m01 * m12 - m02 * m11;
        float c11 = m00 * m22 - m02 * m02;
        float c12 = m01 * m02 - m00 * m12;
        float c22 = m00 * m11 - m01 * m01;
        float det = m00 * c00 + m01 * c01 + m02 * c02;
        float id  = 1.f / det;

        float A0 = (cy0 * c00 + cy1 * c01 + cy2 * c02) * id;
        float A1 = (cy0 * c01 + cy1 * c11 + cy2 * c12) * id;
        float A2 = (cy0 * c02 + cy1 * c12 + cy2 * c22) * id;
        float b  = my - (A0 * mx0 + A1 * mx1 + A2 * mx2);

        g_s2[ob + 0 * HW + row * WW] = A0;
        g_s2[ob + 1 * HW + row * WW] = A1;
        g_s2[ob + 2 * HW + row * WW] = A2;
        g_s2[ob + 3 * HW + row * WW] = b;

        if (row - RAD >= 0) {
            #pragma unroll
            for (int c = 0; c < 13; c++) s[c] -= g_s1[base + c * HW + (row - RAD) * WW];
        }
    }
}

// ---------------------------------------------------------------------------
// K3: per-row horizontal 9-tap box sums of A0,A1,A2,b.
// ---------------------------------------------------------------------------
__global__ void k3_hbox() {
    const int row = blockIdx.x;
    const int n   = blockIdx.y;
    __shared__ float sp[4][WW];

    const int ib = n * 4 * HW + row * WW;
    for (int j = threadIdx.x; j < WW; j += blockDim.x) {
        #pragma unroll
        for (int c = 0; c < 4; c++) sp[c][j] = g_s2[ib + c * HW + j];
    }
    __syncthreads();

    for (int j = threadIdx.x; j < WW; j += blockDim.x) {
        int j0 = j - RAD; if (j0 < 0) j0 = 0;
        int j1 = j + RAD; if (j1 > WW - 1) j1 = WW - 1;
        float s[4];
        #pragma unroll
        for (int c = 0; c < 4; c++) s[c] = 0.f;
        for (int t = j0; t <= j1; t++) {
            #pragma unroll
            for (int c = 0; c < 4; c++) s[c] += sp[c][t];
        }
        #pragma unroll
        for (int c = 0; c < 4; c++) g_s3[ib + c * HW + j] = s[c];
    }
}

// ---------------------------------------------------------------------------
// K4: vertical sliding-window sums of A,b + final output.
// out = mean_A . x + mean_b = (sumA . x + sumb) / N
// ---------------------------------------------------------------------------
__global__ void k4_final(const float* __restrict__ x, float* __restrict__ out) {
    const int col = blockIdx.x * blockDim.x + threadIdx.x;
    const int n   = blockIdx.y;
    const int s0  = blockIdx.z * SEG;
    if (col >= WW) return;

    const int base = n * 4 * HW + col;
    float s[4];
    #pragma unroll
    for (int c = 0; c < 4; c++) s[c] = 0.f;

    int rlo = s0 - RAD; if (rlo < 0) rlo = 0;
    for (int rr = rlo; rr < s0 + RAD; rr++) {
        #pragma unroll
        for (int c = 0; c < 4; c++) s[c] += g_s3[base + c * HW + rr * WW];
    }

    int cl = col - RAD; if (cl < 0) cl = 0;
    int ch = col + RAD; if (ch > WW - 1) ch = WW - 1;
    const int nx = ch - cl + 1;

    const float* xb = x + (size_t)n * CX * HW + col;
    float* ob = out + (size_t)n * HW + col;

    for (int row = s0; row < s0 + SEG; row++) {
        if (row + RAD < HH) {
            #pragma unroll
            for (int c = 0; c < 4; c++) s[c] += g_s3[base + c * HW + (row + RAD) * WW];
        }
        int r0 = row - RAD; if (r0 < 0) r0 = 0;
        int r1 = row + RAD; if (r1 > HH - 1) r1 = HH - 1;
        const int ny = r1 - r0 + 1;
        const float invN = 1.f / (float)(nx * ny);

        float x0 = xb[row * WW];
        float x1 = xb[HW + row * WW];
        float x2 = xb[2 * HW + row * WW];
        ob[row * WW] = (s[0] * x0 + s[1] * x1 + s[2] * x2 + s[3]) * invN;

        if (row - RAD >= 0) {
            #pragma unroll
            for (int c = 0; c < 4; c++) s[c] -= g_s3[base + c * HW + (row - RAD) * WW];
        }
    }
}

extern "C" void kernel_launch(void* const* d_in, const int* in_sizes, int n_in,
                              void* d_out, int out_size) {
    // metadata order: y (4,1,512,512), x (4,3,512,512); swap defensively by size.
    const float* y = (const float*)d_in[0];
    const float* x = (const float*)d_in[1];
    if (n_in >= 2 && in_sizes[0] == NB * CX * HW) {
        const float* t = y; y = x; x = t;
    }

    dim3 grow(HH, NB);
    dim3 gcol(WW / 128, NB, HH / SEG);

    k1_hbox<<<grow, 256>>>(x, y);
    k2_vsolve<<<gcol, 128>>>();
    k3_hbox<<<grow, 256>>>();
    k4_final<<<gcol, 128>>>(x, (float*)d_out);
}